// round 6
// baseline (speedup 1.0000x reference)
#include <cuda_runtime.h>
#include <cuda_bf16.h>

// NV12 -> RGB, 4K frame. 2 px/thread, warp-contiguous loads (R2 shape),
// smem-staged warp-contiguous stores (full-sector STG.64s).
// d_in[0]: int32 flattened: [0 : 7680*4320) full-res Y, then (2160,3840,2) UV.
// d_in[1]: float32[9] yuv_to_rgb (row-major 3x3), d_in[2]: float32[3] offset.
// out: float32 (2160, 3840, 3): rgb[j] = sum_i (yuv[i]-off[i]) * M[i][j],
// yuv = [Y[2r,2c], U[r,c], V[r,c]].

#define HH 2160
#define HW 3840
#define FULL_W (HW * 2)            // 7680
#define Y_ELEMS (FULL_W * HH * 2)  // 33177600
#define PPR (HW / 2)               // 1920 pairs per row (multiple of 32)
#define NPAIRS (HH * PPR)          // 4147200 = 16200 * 256 exactly

__global__ __launch_bounds__(256)
void nv12_to_rgb_kernel(const int* __restrict__ data,
                        const float* __restrict__ M,
                        const float* __restrict__ off,
                        float* __restrict__ out)
{
    __shared__ float stage[8 * 192];  // 192 floats (768B) per warp

    const int idx  = blockIdx.x * blockDim.x + threadIdx.x;  // pair index
    const int lane = threadIdx.x & 31;
    const int warp = threadIdx.x >> 5;

    const int r = idx / PPR;
    const int c = (idx - r * PPR) * 2;  // even half-res col

    // Warp-contiguous 16B-stride loads: 512B contiguous per warp per LDG.
    const int4 yv = *reinterpret_cast<const int4*>(data + (2 * r) * FULL_W + 2 * c);
    const int4 uv = *reinterpret_cast<const int4*>(data + Y_ELEMS + (r * HW + c) * 2);

    // Matrix + offset: uniform addresses -> L1 broadcast.
    const float m00 = __ldg(M + 0), m01 = __ldg(M + 1), m02 = __ldg(M + 2);
    const float m10 = __ldg(M + 3), m11 = __ldg(M + 4), m12 = __ldg(M + 5);
    const float m20 = __ldg(M + 6), m21 = __ldg(M + 7), m22 = __ldg(M + 8);
    const float o0 = __ldg(off + 0), o1 = __ldg(off + 1), o2 = __ldg(off + 2);

    const float ya = (float)yv.x - o0, yb = (float)yv.z - o0;
    const float ua = (float)uv.x - o1, ub = (float)uv.z - o1;
    const float va = (float)uv.y - o2, vb = (float)uv.w - o2;

    float* ws = stage + warp * 192 + lane * 6;
    ws[0] = ya * m00 + ua * m10 + va * m20;
    ws[1] = ya * m01 + ua * m11 + va * m21;
    ws[2] = ya * m02 + ua * m12 + va * m22;
    ws[3] = yb * m00 + ub * m10 + vb * m20;
    ws[4] = yb * m01 + ub * m11 + vb * m21;
    ws[5] = yb * m02 + ub * m12 + vb * m22;

    __syncwarp();

    // Warp's 32 pairs are contiguous and never straddle a row boundary:
    // one contiguous 768B output run. Store lane-contiguous float2s.
    const int warp_pair0 = blockIdx.x * blockDim.x + warp * 32;
    float2* ob = reinterpret_cast<float2*>(out + warp_pair0 * 6);
    const float2* ws2 = reinterpret_cast<const float2*>(stage + warp * 192);

    ob[lane]      = ws2[lane];
    ob[lane + 32] = ws2[lane + 32];
    ob[lane + 64] = ws2[lane + 64];
}

extern "C" void kernel_launch(void* const* d_in, const int* in_sizes, int n_in,
                              void* d_out, int out_size)
{
    const int*   data = (const int*)d_in[0];
    const float* M    = (const float*)d_in[1];
    const float* off  = (const float*)d_in[2];
    float*       out  = (float*)d_out;

    const int threads = 256;
    const int blocks  = NPAIRS / threads;  // 16200 exactly, no tail
    nv12_to_rgb_kernel<<<blocks, threads>>>(data, M, off, out);
}